// round 5
// baseline (speedup 1.0000x reference)
#include <cuda_runtime.h>
#include <cuda_bf16.h>

// Problem constants (fixed by reference)
#define M_PTS 4096
#define N_NODES 1024
#define HID 8
#define NUM 5

#define BLOCK_THREADS 128

// ---------------------------------------------------------------------------
// double-float (two-float) arithmetic: ~2^-44 relative accuracy on FMA pipe
// ---------------------------------------------------------------------------
struct df { float hi, lo; };

__device__ __forceinline__ df two_sum(float a, float b) {
    float s  = a + b;
    float bb = s - a;
    float e  = (a - (s - bb)) + (b - bb);
    return {s, e};
}
__device__ __forceinline__ df quick2(float a, float b) {   // requires |a|>=|b|
    float s = a + b;
    float e = b - (s - a);
    return {s, e};
}
__device__ __forceinline__ df two_prod(float a, float b) {
    float p = a * b;
    float e = fmaf(a, b, -p);
    return {p, e};
}
__device__ __forceinline__ df df_add(df A, df B) {
    df s = two_sum(A.hi, B.hi);
    s.lo += A.lo + B.lo;
    return quick2(s.hi, s.lo);
}
__device__ __forceinline__ df df_addf(df A, float b) {
    df s = two_sum(A.hi, b);
    s.lo += A.lo;
    return quick2(s.hi, s.lo);
}
__device__ __forceinline__ df df_neg(df A) { return {-A.hi, -A.lo}; }
__device__ __forceinline__ df df_sub(df A, df B) { return df_add(A, df_neg(B)); }
__device__ __forceinline__ df df_mul(df A, df B) {
    df p = two_prod(A.hi, B.hi);
    p.lo = fmaf(A.hi, B.lo, fmaf(A.lo, B.hi, p.lo));
    return quick2(p.hi, p.lo);
}
__device__ __forceinline__ df df_mulf(df A, float b) {
    df p = two_prod(A.hi, b);
    p.lo = fmaf(A.lo, b, p.lo);
    return quick2(p.hi, p.lo);
}
__device__ __forceinline__ df df_div(df A, df B) {
    float q1 = A.hi / B.hi;
    df r = df_sub(A, df_mulf(B, q1));
    float q2 = (r.hi + r.lo) / B.hi;
    return quick2(q1, q2);
}
__device__ __forceinline__ df df_sqrt(df A) {
    float y = sqrtf(A.hi);
    if (!(y > 0.0f)) return {0.0f, 0.0f};
    df y2 = two_prod(y, y);
    df r  = df_sub(A, y2);
    float c = (r.hi + r.lo) / (2.0f * y);
    return quick2(y, c);
}

// DF constants carrying the fp64 residual (computed at compile time in double)
#define DF_CONST(name, dval) \
    const df name = { (float)(dval), (float)((dval) - (double)(float)(dval)) }

// ---------------------------------------------------------------------------
// One block per output row m.
// Phase A (fp32): screen all N nodes by dist^2, deterministic prefix-scan
//                 compaction of active node (x, y, w) into shared memory.
// Phase B (DF):   exact pair diff + full KAN chain in double-float.
// Reduce  (DF):   fixed-order shuffle tree; u[m] = T/(S + 1e-10).
// ---------------------------------------------------------------------------
__global__ __launch_bounds__(BLOCK_THREADS)
void meshfree_kan_kernel(const float* __restrict__ x,      // [M,2]
                         const float* __restrict__ nodes,  // [N,2]
                         const float* __restrict__ W1a,    // [HID,NUM]
                         const float* __restrict__ W1b,    // [HID,NUM]
                         const float* __restrict__ W2,     // [HID*NUM]
                         const float* __restrict__ w,      // [N,1]
                         float* __restrict__ out)          // [M,1]
{
    __shared__ float sW1a[HID * NUM];
    __shared__ float sW1b[HID * NUM];
    __shared__ float sW2 [HID * NUM];
    __shared__ float s_nx[N_NODES];
    __shared__ float s_ny[N_NODES];
    __shared__ float s_wn[N_NODES];
    __shared__ int   warpCnt[BLOCK_THREADS / 32];
    __shared__ float redS[2 * (BLOCK_THREADS / 32)];
    __shared__ float redT[2 * (BLOCK_THREADS / 32)];

    DF_CONST(INV_R,  1.0 / 0.3);           // 1/RADIUS  (fp64 value)
    DF_CONST(KGRID,  1.0 / 0.3 / 0.75);    // 1/(RADIUS*H): diff -> grid coord
    DF_CONST(INV_H,  1.0 / 0.75);          // 1/H

    const int m    = blockIdx.x;
    const int tid  = threadIdx.x;
    const int lane = tid & 31;
    const int warp = tid >> 5;

    if (tid < HID * NUM) {
        sW1a[tid] = W1a[tid];
        sW1b[tid] = W1b[tid];
        sW2 [tid] = W2 [tid];
    }

    const float2 xm = reinterpret_cast<const float2*>(x)[m];
    __syncthreads();

    // ---------------- Phase A: fp32 screen + deterministic compaction ------
    const float2* nodes2 = reinterpret_cast<const float2*>(nodes);
    const float R2 = 0.3f * 0.3f * 1.0001f;   // inflated; DF q-clamp in phase B

    int runBase = 0;   // identical in every thread's registers

    #pragma unroll
    for (int k = 0; k < N_NODES / BLOCK_THREADS; k++) {
        const int n = tid + k * BLOCK_THREADS;
        const float2 nd = nodes2[n];
        const float dx = xm.x - nd.x;
        const float dy = xm.y - nd.y;
        const bool act = (dx * dx + dy * dy <= R2);

        const unsigned msk = __ballot_sync(0xffffffffu, act);
        if (lane == 0) warpCnt[warp] = __popc(msk);
        __syncthreads();

        int base = runBase;
        #pragma unroll
        for (int j = 0; j < BLOCK_THREADS / 32; j++) {
            const int c = warpCnt[j];
            if (j < warp) base += c;
            runBase += c;
        }

        if (act) {
            const int off = base + __popc(msk & ((1u << lane) - 1u));
            s_nx[off] = nd.x;
            s_ny[off] = nd.y;
            s_wn[off] = w[n];
        }
        __syncthreads();   // protect warpCnt before next iteration rewrites it
    }
    const int cnt = runBase;

    // ---------------- Phase B: double-float KAN on active pairs ------------
    df S = {0.0f, 0.0f}, T = {0.0f, 0.0f};

    for (int i = tid; i < cnt; i += BLOCK_THREADS) {
        // exact pair differences
        const df dxd = two_sum(xm.x, -s_nx[i]);
        const df dyd = two_sum(xm.y, -s_ny[i]);

        // dist, q, cubic window: w = 1 - 6q^2 + 8q^3 - 3q^4, zero for q>1
        const df d2   = df_add(df_mul(dxd, dxd), df_mul(dyd, dyd));
        const df dist = df_sqrt(d2);
        const df q    = df_mul(dist, INV_R);
        df win;
        if (q.hi > 1.0f) {
            win = {0.0f, 0.0f};
        } else {
            const df q2 = df_mul(q, q);
            const df q3 = df_mul(q2, q);
            const df q4 = df_mul(q2, q2);
            win = df_addf(df_add(df_add(df_mulf(q2, -6.0f),
                                        df_mulf(q3,  8.0f)),
                                 df_mulf(q4, -3.0f)), 1.0f);
        }

        // Layer 1: grid coord u = kin/H + 2 = diff*KGRID + 2; 2-sparse hats.
        // Active pairs: |diff| <= ~0.3 -> u in [~0.667, ~3.333] -> s0 in [0,3].
        const df ua = df_addf(df_mul(dxd, KGRID), 2.0f);
        const df ub = df_addf(df_mul(dyd, KGRID), 2.0f);
        const float fa = floorf(ua.hi), fb = floorf(ub.hi);
        const int   sa = (int)fa,       sb = (int)fb;
        const df ta  = df_addf(ua, -fa);
        const df tb  = df_addf(ub, -fb);
        const df oma = df_addf(df_neg(ta), 1.0f);
        const df omb = df_addf(df_neg(tb), 1.0f);

        df phi = {0.0f, 0.0f};
        #pragma unroll
        for (int h = 0; h < HID; h++) {
            df hid = df_mulf(oma, sW1a[h * NUM + sa]);
            hid = df_add(hid, df_mulf(ta,  sW1a[h * NUM + sa + 1]));
            hid = df_add(hid, df_mulf(omb, sW1b[h * NUM + sb]));
            hid = df_add(hid, df_mulf(tb,  sW1b[h * NUM + sb + 1]));

            // Layer 2: hat basis of hidden (can leave the grid -> bound-check)
            const df uh = df_addf(df_mul(hid, INV_H), 2.0f);
            const float fh = floorf(uh.hi);
            const int   sh = (int)fh;
            const df th = df_addf(uh, -fh);

            if ((unsigned)sh <= (unsigned)(NUM - 1)) {
                const df omh = df_addf(df_neg(th), 1.0f);
                phi = df_add(phi, df_mulf(omh, sW2[h * NUM + sh]));
            }
            if ((unsigned)(sh + 1) <= (unsigned)(NUM - 1)) {
                phi = df_add(phi, df_mulf(th, sW2[h * NUM + sh + 1]));
            }
        }

        const df pw = df_mul(phi, win);
        S = df_add(S, pw);
        T = df_add(T, df_mulf(pw, s_wn[i]));
    }

    // ---------------- Fixed-order DF reduction -----------------------------
    #pragma unroll
    for (int o = 16; o > 0; o >>= 1) {
        df So, To;
        So.hi = __shfl_down_sync(0xffffffffu, S.hi, o);
        So.lo = __shfl_down_sync(0xffffffffu, S.lo, o);
        To.hi = __shfl_down_sync(0xffffffffu, T.hi, o);
        To.lo = __shfl_down_sync(0xffffffffu, T.lo, o);
        S = df_add(S, So);
        T = df_add(T, To);
    }
    if (lane == 0) {
        redS[2 * warp] = S.hi;  redS[2 * warp + 1] = S.lo;
        redT[2 * warp] = T.hi;  redT[2 * warp + 1] = T.lo;
    }
    __syncthreads();
    if (tid == 0) {
        df Sf = {redS[0], redS[1]};
        df Tf = {redT[0], redT[1]};
        #pragma unroll
        for (int j = 1; j < BLOCK_THREADS / 32; j++) {
            Sf = df_add(Sf, {redS[2 * j], redS[2 * j + 1]});
            Tf = df_add(Tf, {redT[2 * j], redT[2 * j + 1]});
        }
        const df den = df_addf(Sf, 1e-10f);
        const df u   = df_div(Tf, den);
        out[m] = u.hi + u.lo;
    }
}

extern "C" void kernel_launch(void* const* d_in, const int* in_sizes, int n_in,
                              void* d_out, int out_size) {
    const float* x     = (const float*)d_in[0];  // [4096,2]
    const float* nodes = (const float*)d_in[1];  // [1024,2]
    const float* W1a   = (const float*)d_in[2];  // [8,5]
    const float* W1b   = (const float*)d_in[3];  // [8,5]
    const float* W2    = (const float*)d_in[4];  // [1,40]
    const float* w     = (const float*)d_in[5];  // [1024,1]
    float* out = (float*)d_out;                  // [4096,1]

    meshfree_kan_kernel<<<M_PTS, BLOCK_THREADS>>>(x, nodes, W1a, W1b, W2, w, out);
}

// round 6
// speedup vs baseline: 1.3361x; 1.3361x over previous
#include <cuda_runtime.h>
#include <cuda_bf16.h>

// Problem constants (fixed by reference)
#define M_PTS 4096
#define N_NODES 1024
#define HID 8
#define NUM 5

#define BLOCK_THREADS 128

// ---------------------------------------------------------------------------
// double-float arithmetic
// ---------------------------------------------------------------------------
struct df { float hi, lo; };

__device__ __forceinline__ df two_sum(float a, float b) {
    float s  = a + b;
    float bb = s - a;
    float e  = (a - (s - bb)) + (b - bb);
    return {s, e};
}
__device__ __forceinline__ df quick2(float a, float b) {   // requires |a|>=|b|
    float s = a + b;
    float e = b - (s - a);
    return {s, e};
}
__device__ __forceinline__ df two_prod(float a, float b) {
    float p = a * b;
    float e = fmaf(a, b, -p);
    return {p, e};
}

// ---- sloppy (no-renorm) ops for the hot loop ----
__device__ __forceinline__ df sadd(df A, df B) {
    df s = two_sum(A.hi, B.hi);
    return {s.hi, s.lo + A.lo + B.lo};
}
__device__ __forceinline__ df saddf(df A, float b) {
    df s = two_sum(A.hi, b);
    return {s.hi, s.lo + A.lo};
}
__device__ __forceinline__ df smul(df A, df B) {
    df p = two_prod(A.hi, B.hi);
    return {p.hi, fmaf(A.hi, B.lo, fmaf(A.lo, B.hi, p.lo))};
}
__device__ __forceinline__ df smulf(df A, float b) {
    df p = two_prod(A.hi, b);
    return {p.hi, fmaf(A.lo, b, p.lo)};
}

// ---- full-precision ops for the epilogue (rare) ----
__device__ __forceinline__ df df_add(df A, df B) {
    df s = two_sum(A.hi, B.hi);
    s.lo += A.lo + B.lo;
    return quick2(s.hi, s.lo);
}
__device__ __forceinline__ df df_addf(df A, float b) {
    df s = two_sum(A.hi, b);
    s.lo += A.lo;
    return quick2(s.hi, s.lo);
}
__device__ __forceinline__ df df_neg(df A) { return {-A.hi, -A.lo}; }
__device__ __forceinline__ df df_mulf(df A, float b) {
    df p = two_prod(A.hi, b);
    p.lo = fmaf(A.lo, b, p.lo);
    return quick2(p.hi, p.lo);
}
__device__ __forceinline__ df df_sub(df A, df B) { return df_add(A, df_neg(B)); }
__device__ __forceinline__ df df_div(df A, df B) {
    float q1 = A.hi / B.hi;
    df r = df_sub(A, df_mulf(B, q1));
    float q2 = (r.hi + r.lo) / B.hi;
    return quick2(q1, q2);
}

// DF constants carrying the fp64 residual
#define DF_CONST(name, dval) \
    const df name = { (float)(dval), (float)((dval) - (double)(float)(dval)) }

// ---------------------------------------------------------------------------
// One block per output row m.
// Tables: difference-form hat weights (exact DF via two_sum), built per block.
// Phase A (fp32): screen all N nodes, deterministic compaction (1 bar/iter).
// Phase B (DF, sloppy): 2-sparse hats in difference form, branch-free layer 2.
// Reduce  (DF): fixed-order shuffle tree; u[m] = T/(S + 1e-10).
// ---------------------------------------------------------------------------
__global__ __launch_bounds__(BLOCK_THREADS)
void meshfree_kan_kernel(const float* __restrict__ x,      // [M,2]
                         const float* __restrict__ nodes,  // [N,2]
                         const float* __restrict__ W1a,    // [HID,NUM]
                         const float* __restrict__ W1b,    // [HID,NUM]
                         const float* __restrict__ W2,     // [HID*NUM]
                         const float* __restrict__ w,      // [N,1]
                         float* __restrict__ out)          // [M,1]
{
    __shared__ float2 s_nxy [N_NODES];       // compacted node coords
    __shared__ float  s_wn  [N_NODES];       // compacted node weights
    __shared__ float2 s_sAB [16 * HID];      // DF: W1a[h][sa] + W1b[h][sb]
    __shared__ float2 s_dA  [4 * HID];       // DF: W1a[h][sa+1] - W1a[h][sa]
    __shared__ float2 s_dB  [4 * HID];       // DF: W1b[h][sb+1] - W1b[h][sb]
    __shared__ float2 s_dif2[9 * HID];       // DF: extended layer-2 slope table
    __shared__ float  s_bas2[9 * HID];       // fp32 exact: layer-2 base table
    __shared__ int    warpCnt[8][4];
    __shared__ float  redS[8], redT[8];

    DF_CONST(INV_R,  1.0 / 0.3);             // 1/RADIUS
    DF_CONST(KGRID,  1.0 / 0.3 / 0.75);      // diff -> layer-1 grid coord scale
    DF_CONST(INV_H,  1.0 / 0.75);            // 1/H

    const int m    = blockIdx.x;
    const int tid  = threadIdx.x;
    const int lane = tid & 31;
    const int warp = tid >> 5;

    // ---------------- Table init (all exact via two_sum) -------------------
    {   // sAB: 16 (sa,sb) combos x 8 h = 128 entries, one per thread
        const int h  = tid & 7;
        const int sa = (tid >> 5) & 3;
        const int sb = (tid >> 3) & 3;
        const df v = two_sum(W1a[h * NUM + sa], W1b[h * NUM + sb]);
        s_sAB[((sa << 2) | sb) * HID + h] = make_float2(v.hi, v.lo);
    }
    if (tid < 32) {
        const int sa = tid >> 3, h = tid & 7;
        const df v = two_sum(W1a[h * NUM + sa + 1], -W1a[h * NUM + sa]);
        s_dA[sa * HID + h] = make_float2(v.hi, v.lo);
    } else if (tid < 64) {
        const int t = tid - 32, sb = t >> 3, h = t & 7;
        const df v = two_sum(W1b[h * NUM + sb + 1], -W1b[h * NUM + sb]);
        s_dB[sb * HID + h] = make_float2(v.hi, v.lo);
    } else if (tid < 64 + 72) {
        const int t = tid - 64, j = t / 8, h = t % 8;   // j in [0,8], sh = j-2
        const int sh = j - 2;
        float base = 0.0f;
        df   dif  = {0.0f, 0.0f};
        if (sh == -1) {
            dif = {W2[h * NUM + 0], 0.0f};
        } else if (sh >= 0 && sh <= 3) {
            base = W2[h * NUM + sh];
            dif  = two_sum(W2[h * NUM + sh + 1], -W2[h * NUM + sh]);
        } else if (sh == 4) {
            base = W2[h * NUM + 4];
            dif  = {-W2[h * NUM + 4], 0.0f};
        }
        s_bas2[j * HID + h] = base;
        s_dif2[j * HID + h] = make_float2(dif.hi, dif.lo);
    }

    const float2 xm = reinterpret_cast<const float2*>(x)[m];

    // ---------------- Phase A: fp32 screen + compaction (1 bar/iter) -------
    const float2* nodes2 = reinterpret_cast<const float2*>(nodes);
    const float R2 = 0.09f * 1.0001f;   // inflated; exact DF q-test in phase B

    int runBase = 0;   // replicated, identical across threads

    #pragma unroll
    for (int k = 0; k < N_NODES / BLOCK_THREADS; k++) {
        const int n = tid + k * BLOCK_THREADS;
        const float2 nd = nodes2[n];
        const float dx = xm.x - nd.x;
        const float dy = xm.y - nd.y;
        const bool act = (fmaf(dx, dx, dy * dy) <= R2);

        const unsigned msk = __ballot_sync(0xffffffffu, act);
        if (lane == 0) warpCnt[k][warp] = __popc(msk);
        __syncthreads();   // per-iter row: no WAR hazard -> single barrier

        int base = runBase;
        #pragma unroll
        for (int j = 0; j < 4; j++) {
            const int c = warpCnt[k][j];
            if (j < warp) base += c;
            runBase += c;
        }

        if (act) {
            const int off = base + __popc(msk & ((1u << lane) - 1u));
            s_nxy[off] = nd;
            s_wn [off] = w[n];
        }
    }
    __syncthreads();   // make compacted data + tables visible
    const int cnt = runBase;

    // ---------------- Phase B: sloppy-DF KAN on active pairs ---------------
    df S = {0.0f, 0.0f}, T = {0.0f, 0.0f};

    for (int i = tid; i < cnt; i += BLOCK_THREADS) {
        const float2 nd = s_nxy[i];
        const float  wn = s_wn[i];

        // exact pair differences
        const df dxd = two_sum(xm.x, -nd.x);
        const df dyd = two_sum(xm.y, -nd.y);

        // d2 = dx^2 + dy^2 (DF)
        df xx; { df p = two_prod(dxd.hi, dxd.hi);
                 xx = {p.hi, fmaf(2.0f * dxd.hi, dxd.lo, p.lo)}; }
        df yy; { df p = two_prod(dyd.hi, dyd.hi);
                 yy = {p.hi, fmaf(2.0f * dyd.hi, dyd.lo, p.lo)}; }
        df d2 = sadd(xx, yy);
        d2 = quick2(d2.hi, d2.lo);          // positive sum: |hi|>=|lo| holds

        // dist = sqrt(d2): fp32 sqrt + one DF Newton step (rsqrt recip)
        df dist;
        if (d2.hi > 0.0f) {
            const float y  = sqrtf(d2.hi);
            const df   y2  = two_prod(y, y);
            const float r  = ((d2.hi - y2.hi) - y2.lo) + d2.lo;
            const float c  = r * (0.5f * rsqrtf(d2.hi));
            dist = quick2(y, c);
        } else {
            dist = {0.0f, 0.0f};
        }

        const df q = smul(dist, INV_R);
        const float qq = (q.hi - 1.0f) + q.lo;   // >0 <=> q>1

        // cubic window: 1 + q^2*(-6 + q*(8 - 3q))
        df win;
        {
            df q2; { df p = two_prod(q.hi, q.hi);
                     q2 = {p.hi, fmaf(2.0f * q.hi, q.lo, p.lo)}; }
            df t1; { df p = two_prod(3.0f, q.hi);
                     df s = two_sum(8.0f, -p.hi);
                     t1 = {s.hi, s.lo - fmaf(3.0f, q.lo, p.lo)}; }
            const df t2 = smul(q, t1);
            const df t3 = saddf(t2, -6.0f);
            const df t4 = smul(q2, t3);
            win = saddf(t4, 1.0f);
            if (qq > 0.0f) win = {0.0f, 0.0f};
        }

        // layer-1 grid coords: u = diff*KGRID + 2; active -> s in [0,3]
        const df ua = saddf(smul(dxd, KGRID), 2.0f);
        const df ub = saddf(smul(dyd, KGRID), 2.0f);
        const float fa = floorf(ua.hi), fb = floorf(ub.hi);
        int sa = (int)fa, sb = (int)fb;
        sa = min(max(sa, 0), 3);
        sb = min(max(sb, 0), 3);
        const df ta = {ua.hi - fa, ua.lo};   // hi-part subtraction is exact
        const df tb = {ub.hi - fb, ub.lo};

        const float2* pAB = s_sAB + ((sa << 2) | sb) * HID;
        const float2* pdA = s_dA + sa * HID;
        const float2* pdB = s_dB + sb * HID;

        df phi = {0.0f, 0.0f};
        #pragma unroll
        for (int h = 0; h < HID; h++) {
            const float2 ab = pAB[h];
            const float2 da = pdA[h];
            const float2 db = pdB[h];

            // hid = (A0+B0) + ta*dA + tb*dB
            df p1; { df p = two_prod(ta.hi, da.x);
                     p1 = {p.hi, fmaf(ta.hi, da.y, fmaf(ta.lo, da.x, p.lo))}; }
            df p2; { df p = two_prod(tb.hi, db.x);
                     p2 = {p.hi, fmaf(tb.hi, db.y, fmaf(tb.lo, db.x, p.lo))}; }
            const df hid = sadd(sadd({ab.x, ab.y}, p1), p2);

            // layer 2 (branch-free): contrib = bas2[j] + th*dif2[j]
            const df uh = saddf(smul(hid, INV_H), 2.0f);
            const float fh = floorf(uh.hi);
            const int j = min(max((int)fh + 2, 0), 8);
            const df th = {uh.hi - fh, uh.lo};

            const float2 dv = s_dif2[j * HID + h];
            const float  bv = s_bas2[j * HID + h];
            df pb; { df p = two_prod(th.hi, dv.x);
                     pb = {p.hi, fmaf(th.hi, dv.y, fmaf(th.lo, dv.x, p.lo))}; }
            phi = sadd(phi, pb);
            phi = saddf(phi, bv);
        }

        // renormalize (two_sum: safe under cancellation), apply window
        const df pn = two_sum(phi.hi, phi.lo);
        const df wn2 = two_sum(win.hi, win.lo);
        const df pw = smul(pn, wn2);
        S = sadd(S, pw);
        T = sadd(T, smulf(pw, wn));
    }

    // ---------------- Fixed-order DF reduction -----------------------------
    #pragma unroll
    for (int o = 16; o > 0; o >>= 1) {
        df So, To;
        So.hi = __shfl_down_sync(0xffffffffu, S.hi, o);
        So.lo = __shfl_down_sync(0xffffffffu, S.lo, o);
        To.hi = __shfl_down_sync(0xffffffffu, T.hi, o);
        To.lo = __shfl_down_sync(0xffffffffu, T.lo, o);
        S = sadd(S, So);
        T = sadd(T, To);
    }
    if (lane == 0) {
        redS[2 * warp] = S.hi;  redS[2 * warp + 1] = S.lo;
        redT[2 * warp] = T.hi;  redT[2 * warp + 1] = T.lo;
    }
    __syncthreads();
    if (tid == 0) {
        df Sf = two_sum(redS[0], redS[1]);
        df Tf = two_sum(redT[0], redT[1]);
        #pragma unroll
        for (int j = 1; j < 4; j++) {
            Sf = df_add(Sf, two_sum(redS[2 * j], redS[2 * j + 1]));
            Tf = df_add(Tf, two_sum(redT[2 * j], redT[2 * j + 1]));
        }
        const df den = df_addf(Sf, 1e-10f);
        const df u   = df_div(Tf, den);
        out[m] = u.hi + u.lo;
    }
}

extern "C" void kernel_launch(void* const* d_in, const int* in_sizes, int n_in,
                              void* d_out, int out_size) {
    const float* x     = (const float*)d_in[0];  // [4096,2]
    const float* nodes = (const float*)d_in[1];  // [1024,2]
    const float* W1a   = (const float*)d_in[2];  // [8,5]
    const float* W1b   = (const float*)d_in[3];  // [8,5]
    const float* W2    = (const float*)d_in[4];  // [1,40]
    const float* w     = (const float*)d_in[5];  // [1024,1]
    float* out = (float*)d_out;                  // [4096,1]

    meshfree_kan_kernel<<<M_PTS, BLOCK_THREADS>>>(x, nodes, W1a, W1b, W2, w, out);
}

// round 10
// speedup vs baseline: 1.6413x; 1.2284x over previous
#include <cuda_runtime.h>
#include <cuda_bf16.h>

// Problem constants (fixed by reference)
#define M_PTS 4096
#define N_NODES 1024
#define HID 8
#define NUM 5

#define ROWS_PER_BLOCK 4
#define BLOCK_THREADS 128
#define CAP 256            // max active nodes per row (mean ~72, >20 sigma safe)

// ---------------------------------------------------------------------------
// double-float arithmetic
// ---------------------------------------------------------------------------
struct df { float hi, lo; };

__device__ __forceinline__ df two_sum(float a, float b) {
    float s  = a + b;
    float bb = s - a;
    float e  = (a - (s - bb)) + (b - bb);
    return {s, e};
}
__device__ __forceinline__ df quick2(float a, float b) {   // requires |a|>=|b|
    float s = a + b;
    float e = b - (s - a);
    return {s, e};
}
__device__ __forceinline__ df two_prod(float a, float b) {
    float p = a * b;
    float e = fmaf(a, b, -p);
    return {p, e};
}
// sloppy (no renorm) hot-loop ops
__device__ __forceinline__ df sadd(df A, df B) {
    df s = two_sum(A.hi, B.hi);
    return {s.hi, s.lo + A.lo + B.lo};
}
__device__ __forceinline__ df saddf(df A, float b) {
    df s = two_sum(A.hi, b);
    return {s.hi, s.lo + A.lo};
}
__device__ __forceinline__ df smul(df A, df B) {
    df p = two_prod(A.hi, B.hi);
    return {p.hi, fmaf(A.hi, B.lo, fmaf(A.lo, B.hi, p.lo))};
}
__device__ __forceinline__ df smulf(df A, float b) {
    df p = two_prod(A.hi, b);
    return {p.hi, fmaf(A.lo, b, p.lo)};
}
// full-precision epilogue / init ops
__device__ __forceinline__ df df_add(df A, df B) {
    df s = two_sum(A.hi, B.hi);
    s.lo += A.lo + B.lo;
    return quick2(s.hi, s.lo);
}
__device__ __forceinline__ df df_addf(df A, float b) {
    df s = two_sum(A.hi, b);
    s.lo += A.lo;
    return quick2(s.hi, s.lo);
}
__device__ __forceinline__ df df_neg(df A) { return {-A.hi, -A.lo}; }
__device__ __forceinline__ df df_mul(df A, df B) {
    df p = two_prod(A.hi, B.hi);
    p.lo = fmaf(A.hi, B.lo, fmaf(A.lo, B.hi, p.lo));
    return quick2(p.hi, p.lo);
}
__device__ __forceinline__ df df_mulf(df A, float b) {
    df p = two_prod(A.hi, b);
    p.lo = fmaf(A.lo, b, p.lo);
    return quick2(p.hi, p.lo);
}
__device__ __forceinline__ df df_sub(df A, df B) { return df_add(A, df_neg(B)); }
__device__ __forceinline__ df df_div(df A, df B) {
    float q1 = A.hi / B.hi;
    df r = df_sub(A, df_mulf(B, q1));
    float q2 = (r.hi + r.lo) / B.hi;
    return quick2(q1, q2);
}

#define DF_CONST(name, dval) \
    const df name = { (float)(dval), (float)((dval) - (double)(float)(dval)) }

// ---------------------------------------------------------------------------
// One WARP per output row m; 4 rows per 128-thread block; grid = 1024 blocks.
// Tables (h-major, pre-scaled by 1/H, packed float2/float4) built per block.
// Phase A: warp-private ballot compaction of active nodes (no barriers).
// Phase B: sloppy-DF KAN, hats in difference form, branch-free exact layer 2.
// Reduce : warp shuffle tree only; lane 0 computes u = T/(S+1e-10).
// ---------------------------------------------------------------------------
__global__ __launch_bounds__(BLOCK_THREADS)
void meshfree_kan_kernel(const float* __restrict__ x,      // [M,2]
                         const float* __restrict__ nodes,  // [N,2]
                         const float* __restrict__ W1a,    // [HID,NUM]
                         const float* __restrict__ W1b,    // [HID,NUM]
                         const float* __restrict__ W2,     // [HID*NUM]
                         const float* __restrict__ w,      // [N,1]
                         float* __restrict__ out)          // [M,1]
{
    __shared__ float2 sT1ab[HID * 16];            // [h][combo]: (A0+B0)/H + 2 (DF)
    __shared__ float4 sT1d [HID * 16];            // [h][combo]: {dA/H (DF), dB/H (DF)}
    __shared__ float4 sT2  [HID * 9];             // [h][j]: {bas, dif.hi, dif.lo, 0}
    __shared__ float2 s_nxy[ROWS_PER_BLOCK][CAP]; // compacted node coords
    __shared__ float  s_wn [ROWS_PER_BLOCK][CAP]; // compacted node weights

    DF_CONST(KGRID,  1.0 / 0.3 / 0.75);   // diff -> layer-1 grid coordinate
    DF_CONST(INV_H,  1.0 / 0.75);
    DF_CONST(INV_R2, 1.0 / 0.09);         // 1/RADIUS^2

    const int tid  = threadIdx.x;
    const int lane = tid & 31;
    const int warp = tid >> 5;

    // ---------------- Table init (exact DF; one entry per thread) ----------
    {
        const int h     = tid & 7;
        const int combo = tid >> 3;             // 0..15
        const int sa    = combo >> 2, sb = combo & 3;
        const float a0 = W1a[h * NUM + sa], a1 = W1a[h * NUM + sa + 1];
        const float b0 = W1b[h * NUM + sb], b1 = W1b[h * NUM + sb + 1];
        const df ab = df_addf(df_mul(two_sum(a0, b0), INV_H), 2.0f);
        sT1ab[h * 16 + combo] = make_float2(ab.hi, ab.lo);
        const df da = df_mul(two_sum(a1, -a0), INV_H);
        const df db = df_mul(two_sum(b1, -b0), INV_H);
        sT1d[h * 16 + combo] = make_float4(da.hi, da.lo, db.hi, db.lo);
    }
    if (tid < HID * 9) {
        const int h = tid & 7;
        const int j = tid >> 3;                 // 0..8, sh = j-2
        const int sh = j - 2;
        float bas = 0.0f;
        df   dif = {0.0f, 0.0f};
        if (sh == -1) {
            dif = {W2[h * NUM + 0], 0.0f};
        } else if (sh >= 0 && sh <= 3) {
            bas = W2[h * NUM + sh];
            dif = two_sum(W2[h * NUM + sh + 1], -W2[h * NUM + sh]);
        } else if (sh == 4) {
            bas = W2[h * NUM + 4];
            dif = {-W2[h * NUM + 4], 0.0f};
        }
        sT2[h * 9 + j] = make_float4(bas, dif.hi, dif.lo, 0.0f);
    }

    const int m = blockIdx.x * ROWS_PER_BLOCK + warp;
    const float2 xm = reinterpret_cast<const float2*>(x)[m];

    // ---------------- Phase A: warp-private scan + compaction --------------
    const float2* nodes2 = reinterpret_cast<const float2*>(nodes);
    const float R2 = 0.09f * 1.0001f;   // inflated; exact window-zero in phase B

    int cnt = 0;
    #pragma unroll 8
    for (int k = 0; k < N_NODES / 32; k++) {
        const int n = k * 32 + lane;
        const float2 nd = nodes2[n];
        const float dx = xm.x - nd.x;
        const float dy = xm.y - nd.y;
        const bool act = (fmaf(dx, dx, dy * dy) <= R2);

        const unsigned msk = __ballot_sync(0xffffffffu, act);
        if (act) {
            const int off = cnt + __popc(msk & ((1u << lane) - 1u));
            if (off < CAP) {
                s_nxy[warp][off] = nd;
                s_wn [warp][off] = w[n];
            }
        }
        cnt += __popc(msk);
    }
    if (cnt > CAP) cnt = CAP;

    __syncthreads();   // tables (cross-warp) + own-row buffers visible

    // ---------------- Phase B: sloppy-DF KAN on active pairs ---------------
    df S = {0.0f, 0.0f}, T = {0.0f, 0.0f};

    for (int i = lane; i < cnt; i += 32) {
        const float2 nd = s_nxy[warp][i];
        const float  wn = s_wn [warp][i];

        // exact pair differences
        const df dxd = two_sum(xm.x, -nd.x);
        const df dyd = two_sum(xm.y, -nd.y);

        // d2 = dx^2 + dy^2, q^2 = d2/R^2, q = sqrt(q2)
        df xx; { df p = two_prod(dxd.hi, dxd.hi);
                 xx = {p.hi, fmaf(2.0f * dxd.hi, dxd.lo, p.lo)}; }
        df yy; { df p = two_prod(dyd.hi, dyd.hi);
                 yy = {p.hi, fmaf(2.0f * dyd.hi, dyd.lo, p.lo)}; }
        df d2 = sadd(xx, yy);
        d2 = quick2(d2.hi, d2.lo);           // positive sum: valid quick2
        const df q2 = smul(d2, INV_R2);

        df q;
        if (q2.hi > 0.0f) {
            const float y  = sqrtf(q2.hi);
            const df   y2  = two_prod(y, y);
            const float r  = ((q2.hi - y2.hi) - y2.lo) + q2.lo;
            const float c  = r * (0.5f * rsqrtf(q2.hi));
            q = quick2(y, c);
        } else {
            q = {0.0f, 0.0f};
        }
        const float qq = (q.hi - 1.0f) + q.lo;   // >0 <=> q>1 (Sterbenz exact)

        // window = (1-q)^3 (1+3q)  ==  1 - 6q^2 + 8q^3 - 3q^4
        df win;
        {
            df omq; { df s = two_sum(1.0f, -q.hi); omq = {s.hi, s.lo - q.lo}; }
            const df omq2 = smul(omq, omq);
            const df omq3 = smul(omq2, omq);
            df p3; { df p = two_prod(3.0f, q.hi);
                     df s = two_sum(1.0f, p.hi);
                     p3 = {s.hi, s.lo + fmaf(3.0f, q.lo, p.lo)}; }
            win = smul(omq3, p3);
            if (qq > 0.0f) win = {0.0f, 0.0f};
        }

        // layer-1 grid coords: u = diff*KGRID + 2; active pairs -> s in [0,3]
        const df ua = saddf(smul(dxd, KGRID), 2.0f);
        const df ub = saddf(smul(dyd, KGRID), 2.0f);
        const float fa = floorf(ua.hi), fb = floorf(ub.hi);
        int sa = (int)fa, sb = (int)fb;
        sa = min(max(sa, 0), 3);
        sb = min(max(sb, 0), 3);
        const df ta = {ua.hi - fa, ua.lo};   // hi subtraction exact
        const df tb = {ub.hi - fb, ub.lo};
        const int co = (sa << 2) | sb;

        df phi = {0.0f, 0.0f};
        #pragma unroll
        for (int h = 0; h < HID; h++) {
            const float2 ab = sT1ab[h * 16 + co];
            const float4 dd = sT1d [h * 16 + co];

            // uh = ab' + ta*dA' + tb*dB'   (already scaled by 1/H, offset +2)
            df p1; { df p = two_prod(ta.hi, dd.x);
                     p1 = {p.hi, fmaf(ta.hi, dd.y, fmaf(ta.lo, dd.x, p.lo))}; }
            df p2; { df p = two_prod(tb.hi, dd.z);
                     p2 = {p.hi, fmaf(tb.hi, dd.w, fmaf(tb.lo, dd.z, p.lo))}; }
            const df uh = sadd(sadd({ab.x, ab.y}, p1), p2);

            // layer 2 (branch-free, exact for all uh): bas[j] + th*dif[j]
            const float fh = floorf(uh.hi);
            const int j = min(max((int)fh + 2, 0), 8);
            const df th = {uh.hi - fh, uh.lo};

            const float4 t2 = sT2[h * 9 + j];
            df pb; { df p = two_prod(th.hi, t2.y);
                     pb = {p.hi, fmaf(th.hi, t2.z, fmaf(th.lo, t2.y, p.lo))}; }
            phi = sadd(phi, pb);
            phi = saddf(phi, t2.x);
        }

        // renormalize (two_sum: safe under cancellation), apply window
        const df pn  = two_sum(phi.hi, phi.lo);
        const df wnd = two_sum(win.hi, win.lo);
        const df pw  = smul(pn, wnd);
        S = sadd(S, pw);
        T = sadd(T, smulf(pw, wn));
    }

    // ---------------- Warp-only fixed-order DF reduction -------------------
    #pragma unroll
    for (int o = 16; o > 0; o >>= 1) {
        df So, To;
        So.hi = __shfl_down_sync(0xffffffffu, S.hi, o);
        So.lo = __shfl_down_sync(0xffffffffu, S.lo, o);
        To.hi = __shfl_down_sync(0xffffffffu, T.hi, o);
        To.lo = __shfl_down_sync(0xffffffffu, T.lo, o);
        S = sadd(S, So);
        T = sadd(T, To);
    }
    if (lane == 0) {
        const df Sf  = two_sum(S.hi, S.lo);
        const df Tf  = two_sum(T.hi, T.lo);
        const df den = df_addf(Sf, 1e-10f);
        const df u   = df_div(Tf, den);
        out[m] = u.hi + u.lo;
    }
}

extern "C" void kernel_launch(void* const* d_in, const int* in_sizes, int n_in,
                              void* d_out, int out_size) {
    const float* x     = (const float*)d_in[0];  // [4096,2]
    const float* nodes = (const float*)d_in[1];  // [1024,2]
    const float* W1a   = (const float*)d_in[2];  // [8,5]
    const float* W1b   = (const float*)d_in[3];  // [8,5]
    const float* W2    = (const float*)d_in[4];  // [1,40]
    const float* w     = (const float*)d_in[5];  // [1024,1]
    float* out = (float*)d_out;                  // [4096,1]

    meshfree_kan_kernel<<<M_PTS / ROWS_PER_BLOCK, BLOCK_THREADS>>>(
        x, nodes, W1a, W1b, W2, w, out);
}